// round 11
// baseline (speedup 1.0000x reference)
#include <cuda_runtime.h>
#include <cuda_fp16.h>
#include <cstdint>
#include <cstring>

#define Bsz 32
#define Ssz 4096
#define Dsz 1280
#define Rsz 64

// fp16 scratch: concatenated pre-rounded params + intermediate H
__device__ __half g_Acat[8 * 128 * Dsz];          // [e][n(128)][k(1280)]
__device__ __half g_Bcat[8 * Dsz * 128];          // [e][d(1280)][k(128)]
__device__ __half g_H[31u * Ssz * 128];           // [b][m][k(128)]

#define STGX 9216           // 64 rows x 144B  (x stage, M=64)
#define STGA 18432          // 128 rows x 144B (A stage, full rank N=128)
#define STGH2 17408         // 64 rows x 272B  (H tile, M=64)
#define STGB 34816          // 128 rows x 272B (B stage)
#define SMEM1 (2 * STGX + 3 * STGA)    // 73728
#define SMEM2 (STGH2 + 2 * STGB)       // 87040

// ---------------------------------------------------------------------------
__device__ __forceinline__ uint32_t smem_u32(const void* p) {
    uint32_t a;
    asm("{ .reg .u64 t; cvta.to.shared.u64 t, %1; cvt.u32.u64 %0, t; }" : "=r"(a) : "l"(p));
    return a;
}
__device__ __forceinline__ unsigned h2u(__half2 h) {
    unsigned u; memcpy(&u, &h, 4); return u;
}
__device__ __forceinline__ void cp16(uint32_t dst, const void* src) {
    asm volatile("cp.async.cg.shared.global [%0], [%1], 16;" :: "r"(dst), "l"(src));
}
__device__ __forceinline__ void commit_group() {
    asm volatile("cp.async.commit_group;" ::: "memory");
}
__device__ __forceinline__ void sts128(uint32_t a, unsigned u0, unsigned u1, unsigned u2, unsigned u3) {
    asm volatile("st.shared.v4.b32 [%0], {%1,%2,%3,%4};" :: "r"(a), "r"(u0), "r"(u1), "r"(u2), "r"(u3));
}
__device__ __forceinline__ void ldsm_x4(unsigned r[4], uint32_t addr) {
    asm volatile("ldmatrix.sync.aligned.m8n8.x4.shared.b16 {%0,%1,%2,%3}, [%4];"
                 : "=r"(r[0]), "=r"(r[1]), "=r"(r[2]), "=r"(r[3]) : "r"(addr));
}
__device__ __forceinline__ void mma16816(float c[4], const unsigned a[4], unsigned b0, unsigned b1) {
    asm volatile(
        "mma.sync.aligned.m16n8k16.row.col.f32.f16.f16.f32 "
        "{%0,%1,%2,%3}, {%4,%5,%6,%7}, {%8,%9}, {%0,%1,%2,%3};"
        : "+f"(c[0]), "+f"(c[1]), "+f"(c[2]), "+f"(c[3])
        : "r"(a[0]), "r"(a[1]), "r"(a[2]), "r"(a[3]), "r"(b0), "r"(b1));
}

// ---------------------------------------------------------------------------
// Pre-convert params to fp16 concatenated layouts (rn rounding).
// ---------------------------------------------------------------------------
__global__ void preconv_kernel(const float* __restrict__ A_exp,
                               const float* __restrict__ B_exp,
                               const float* __restrict__ A_gen,
                               const float* __restrict__ B_gen)
{
    int idx = blockIdx.x * blockDim.x + threadIdx.x;
    const int NA = 8 * 128 * Dsz / 2;
    if (idx < NA) {
        int p = idx * 2;
        int e = p / (128 * Dsz);
        int r = p % (128 * Dsz);
        int n = r / Dsz, k = r % Dsz;
        float f0, f1;
        if (n < Rsz) {
            const float* s = A_exp + ((size_t)e * Rsz + n) * Dsz + k;
            f0 = s[0]; f1 = s[1];
        } else {
            const float* s = A_gen + (size_t)(n - Rsz) * Dsz + k;
            f0 = s[0]; f1 = s[1];
        }
        *reinterpret_cast<__half2*>(&g_Acat[p]) = __floats2half2_rn(f0, f1);

        int e2 = p / (Dsz * 128);
        int r2 = p % (Dsz * 128);
        int d = r2 / 128, k2 = r2 % 128;
        float g0, g1;
        if (k2 < Rsz) {
            const float* s = B_exp + ((size_t)e2 * Dsz + d) * Rsz + k2;
            g0 = s[0]; g1 = s[1];
        } else {
            const float* s = B_gen + (size_t)d * Rsz + (k2 - Rsz);
            g0 = s[0]; g1 = s[1];
        }
        *reinterpret_cast<__half2*>(&g_Bcat[p]) = __floats2half2_rn(g0, g1);
    }
}

// ---------------------------------------------------------------------------
// GEMM1: H[b] (4096x128) = x[b] @ Acat[b]^T, fp16 mma, output fp16 to g_H.
// grid (64, 31) = 1984 CTAs (M tile 64). 256 thr, 8 warps 2Mx4N, warp 32x32.
// K-stage 64, KT=20. x producer decoupled (LDG one iter ahead of STS).
// ---------------------------------------------------------------------------
__global__ __launch_bounds__(256, 2) void gemm1_fp16(
    const float* __restrict__ x,
    const int*   __restrict__ label)
{
    extern __shared__ char smem[];
    const int b   = blockIdx.y;
    const int m0  = blockIdx.x * 64;
    const int e   = __ldg(&label[b]);
    const int tid = threadIdx.x;
    const int warp = tid >> 5, lane = tid & 31;
    const int wm = warp & 1, wn = warp >> 1;        // 2 along M, 4 along N
    const int lg = lane >> 2, lc = lane & 3;

    uint32_t sX = smem_u32(smem);                 // x ring: 2 stages (64 rows)
    uint32_t sA = sX + 2 * STGX;                  // Acat ring: 3 stages (128 rows)

    const char* xb = (const char*)(x + ((size_t)b * Ssz + m0) * Dsz);
    const char* Ab = (const char*)g_Acat + (size_t)e * 128 * Dsz * 2;

    // ldmatrix per-lane offsets (stride 144)
    uint32_t aoff[2], boff[2];
#pragma unroll
    for (int i = 0; i < 2; i++)
        aoff[i] = (uint32_t)((wm * 32 + i * 16 + (lane & 15)) * 144 + ((lane >> 4) << 4));
#pragma unroll
    for (int jp = 0; jp < 2; jp++)
        boff[jp] = (uint32_t)((wn * 32 + jp * 16 + (lane & 7) + ((lane >> 4) << 3)) * 144
                              + (((lane >> 3) & 1) << 4));

    auto cp_A = [&](int j) {
        uint32_t dst = sA + (j % 3) * STGA;
        const char* base = Ab + (size_t)j * 128;   // k-slice: 64 halves = 128B
#pragma unroll
        for (int i = 0; i < 4; i++) {
            int cid = tid + i * 256;               // 1024 chunks (128 rows x 8)
            int row = cid >> 3, g = cid & 7;
            cp16(dst + row * 144 + g * 16, base + (size_t)row * (Dsz * 2) + g * 16);
        }
        commit_group();
    };

    // x pipeline regs: 8 half2 = one 64-row stage per thread
    unsigned xu[8];

    auto ldg_x = [&](int j) {
#pragma unroll
        for (int q = 0; q < 2; q++) {
            int cid = tid + q * 256;               // 512 chunks (64 rows x 8)
            int row = cid >> 3, gp = cid & 7;
            const float4* src = (const float4*)(xb + (size_t)row * (Dsz * 4) + j * 256 + gp * 32);
            float4 a = __ldg(src);
            float4 c = __ldg(src + 1);
            xu[q*4+0] = h2u(__floats2half2_rn(a.x, a.y));
            xu[q*4+1] = h2u(__floats2half2_rn(a.z, a.w));
            xu[q*4+2] = h2u(__floats2half2_rn(c.x, c.y));
            xu[q*4+3] = h2u(__floats2half2_rn(c.z, c.w));
        }
    };
    auto sts_x = [&](int j) {
        uint32_t dst = sX + (j & 1) * STGX;
#pragma unroll
        for (int q = 0; q < 2; q++) {
            int cid = tid + q * 256;
            int row = cid >> 3, gp = cid & 7;
            sts128(dst + row * 144 + gp * 16, xu[q*4+0], xu[q*4+1], xu[q*4+2], xu[q*4+3]);
        }
    };

    // prologue
    cp_A(0);
    cp_A(1);
    ldg_x(0);
    sts_x(0);
    ldg_x(1);          // in flight; STS'd at end of kt=0
    asm volatile("cp.async.wait_group 1;" ::: "memory");
    __syncthreads();

    float acc[2][4][4] = {};

    const int KT = Dsz / 64;    // 20
#pragma unroll 1
    for (int kt = 0; kt < KT; kt++) {
        if (kt + 2 < KT) cp_A(kt + 2);
        else             commit_group();

        uint32_t aS = sX + (kt & 1) * STGX;
        uint32_t bS = sA + (kt % 3) * STGA;

#pragma unroll
        for (int kk = 0; kk < 4; kk++) {
            unsigned af[2][4], bf[2][4];
            uint32_t kb = kk * 32;
#pragma unroll
            for (int i = 0; i < 2; i++) ldsm_x4(af[i], aS + aoff[i] + kb);
#pragma unroll
            for (int jp = 0; jp < 2; jp++) ldsm_x4(bf[jp], bS + boff[jp] + kb);
#pragma unroll
            for (int i = 0; i < 2; i++)
#pragma unroll
                for (int jp = 0; jp < 2; jp++) {
                    mma16816(acc[i][2*jp],   af[i], bf[jp][0], bf[jp][1]);
                    mma16816(acc[i][2*jp+1], af[i], bf[jp][2], bf[jp][3]);
                }
        }

        if (kt + 1 < KT) sts_x(kt + 1);
        if (kt + 2 < KT) ldg_x(kt + 2);

        asm volatile("cp.async.wait_group 1;" ::: "memory");
        __syncthreads();
    }

    // epilogue: H (fp16) -> global
    __half* Hb = g_H + ((size_t)b * Ssz + m0) * 128;
#pragma unroll
    for (int i = 0; i < 2; i++) {
        int r = wm * 32 + i * 16 + lg;
#pragma unroll
        for (int j = 0; j < 4; j++) {
            int c = wn * 32 + j * 8 + lc * 2;
            *reinterpret_cast<__half2*>(Hb + (size_t)r * 128 + c) =
                __floats2half2_rn(acc[i][j][0], acc[i][j][1]);
            *reinterpret_cast<__half2*>(Hb + (size_t)(r + 8) * 128 + c) =
                __floats2half2_rn(acc[i][j][2], acc[i][j][3]);
        }
    }
}

// ---------------------------------------------------------------------------
// GEMM2: out[b] (4096x1280) = 2 * H[b] @ Bcat[b]^T.
// grid (64, 32) = 2048 CTAs (M tile 64). 256 thr, 8 warps 2Mx4N, warp 32x32.
// H tile (64x128) in smem once; loop 10 n-tiles, B ring 2 stages; B prefetch
// overlapped with epilogue stores. b==31 CTAs zero their slice.
// ---------------------------------------------------------------------------
__global__ __launch_bounds__(256, 2) void gemm2_fp16(
    const int* __restrict__ label,
    float*     __restrict__ out)
{
    extern __shared__ char smem[];
    const int b   = blockIdx.y;
    const int m0  = blockIdx.x * 64;
    const int tid = threadIdx.x;

    float* ob = out + ((size_t)b * Ssz + m0) * Dsz;

    if (b == Bsz - 1) {
        float4 z = make_float4(0.f, 0.f, 0.f, 0.f);
#pragma unroll 4
        for (int i = 0; i < 80; i++) {
            int v = tid + i * 256;       // 20480 float4 = 64 rows x 320
            int row = v / 320, c4 = v % 320;
            __stcs((float4*)(ob + (size_t)row * Dsz + c4 * 4), z);
        }
        return;
    }

    const int e = __ldg(&label[b]);
    const int warp = tid >> 5, lane = tid & 31;
    const int wm = warp & 1, wn = warp >> 1;
    const int lg = lane >> 2, lc = lane & 3;

    uint32_t sH = smem_u32(smem);
    uint32_t sB = sH + STGH2;

    // ldmatrix per-lane offsets (stride 272)
    uint32_t aoff[2], boff[2];
#pragma unroll
    for (int i = 0; i < 2; i++)
        aoff[i] = (uint32_t)((wm * 32 + i * 16 + (lane & 15)) * 272 + ((lane >> 4) << 4));
#pragma unroll
    for (int jp = 0; jp < 2; jp++)
        boff[jp] = (uint32_t)((wn * 32 + jp * 16 + (lane & 7) + ((lane >> 4) << 3)) * 272
                              + (((lane >> 3) & 1) << 4));

    // H tile load (once): 64 rows x 16 chunks = 1024
    {
        const char* base = (const char*)g_H + ((size_t)b * Ssz + m0) * 256;
#pragma unroll
        for (int i = 0; i < 4; i++) {
            int cid = tid + i * 256;
            int row = cid >> 4, g = cid & 15;
            cp16(sH + row * 272 + g * 16, base + (size_t)row * 256 + g * 16);
        }
        commit_group();
    }

    auto cp_B = [&](int nt) {
        uint32_t dst = sB + (nt & 1) * STGB;
        const char* base = (const char*)g_Bcat + ((size_t)e * Dsz + nt * 128) * 256;
#pragma unroll
        for (int i = 0; i < 8; i++) {
            int cid = tid + i * 256;               // 2048 chunks (128 rows x 16)
            int row = cid >> 4, g = cid & 15;
            cp16(dst + row * 272 + g * 16, base + (size_t)row * 256 + g * 16);
        }
        commit_group();
    };

    cp_B(0);
    cp_B(1);
    asm volatile("cp.async.wait_group 1;" ::: "memory");   // H + B0 ready
    __syncthreads();

#pragma unroll 1
    for (int nt = 0; nt < 10; nt++) {
        float acc[2][4][4] = {};
        uint32_t bS = sB + (nt & 1) * STGB;

#pragma unroll
        for (int kk = 0; kk < 8; kk++) {
            unsigned af[2][4], bf[2][4];
            uint32_t kb = kk * 32;
#pragma unroll
            for (int i = 0; i < 2; i++) ldsm_x4(af[i], sH + aoff[i] + kb);
#pragma unroll
            for (int jp = 0; jp < 2; jp++) ldsm_x4(bf[jp], bS + boff[jp] + kb);
#pragma unroll
            for (int i = 0; i < 2; i++)
#pragma unroll
                for (int jp = 0; jp < 2; jp++) {
                    mma16816(acc[i][2*jp],   af[i], bf[jp][0], bf[jp][1]);
                    mma16816(acc[i][2*jp+1], af[i], bf[jp][2], bf[jp][3]);
                }
        }

        __syncthreads();                      // all warps done reading slot nt&1
        if (nt + 2 < 10) cp_B(nt + 2);        // refill freed slot, overlaps epilogue
        else             commit_group();

        // epilogue for this n-tile: out = 2*acc (hides B transfer)
        int n0 = nt * 128;
#pragma unroll
        for (int i = 0; i < 2; i++) {
            int r = wm * 32 + i * 16 + lg;
#pragma unroll
            for (int j = 0; j < 4; j++) {
                int c = n0 + wn * 32 + j * 8 + lc * 2;
                __stcs((float2*)&ob[(size_t)r * Dsz + c],
                       make_float2(2.0f * acc[i][j][0], 2.0f * acc[i][j][1]));
                __stcs((float2*)&ob[(size_t)(r + 8) * Dsz + c],
                       make_float2(2.0f * acc[i][j][2], 2.0f * acc[i][j][3]));
            }
        }

        asm volatile("cp.async.wait_group 1;" ::: "memory");   // B(nt+1) complete
        __syncthreads();
    }
}

// ---------------------------------------------------------------------------
extern "C" void kernel_launch(void* const* d_in, const int* in_sizes, int n_in,
                              void* d_out, int out_size)
{
    const float* x     = (const float*)d_in[0];
    // d_in[1] = weight : unused by the reference
    const float* A_exp = (const float*)d_in[2];
    const float* B_exp = (const float*)d_in[3];
    const float* A_gen = (const float*)d_in[4];
    const float* B_gen = (const float*)d_in[5];
    const int*   label = (const int*)d_in[6];
    float* out = (float*)d_out;

    cudaFuncSetAttribute(gemm1_fp16, cudaFuncAttributeMaxDynamicSharedMemorySize, SMEM1);
    cudaFuncSetAttribute(gemm2_fp16, cudaFuncAttributeMaxDynamicSharedMemorySize, SMEM2);

    preconv_kernel<<<(8 * 128 * Dsz / 2 + 255) / 256, 256>>>(A_exp, B_exp, A_gen, B_gen);
    gemm1_fp16<<<dim3(Ssz / 64, Bsz - 1), 256, SMEM1>>>(x, label);
    gemm2_fp16<<<dim3(Ssz / 64, Bsz), 256, SMEM2>>>(label, out);
}

// round 12
// speedup vs baseline: 1.2079x; 1.2079x over previous
#include <cuda_runtime.h>
#include <cuda_fp16.h>
#include <cstdint>
#include <cstring>

#define Bsz 32
#define Ssz 4096
#define Dsz 1280
#define Rsz 64

// fp16 scratch: concatenated pre-rounded params + intermediate H
__device__ __half g_Acat[8 * 128 * Dsz];          // [e][n(128)][k(1280)]
__device__ __half g_Bcat[8 * Dsz * 128];          // [e][d(1280)][k(128)], pre-scaled by ALPHA
__device__ __half g_H[31u * Ssz * 128];           // [b][m][k(128)]

#define STGA 18432          // 128 rows x 144B (64 halves + pad)
#define STGH 34816          // 128 rows x 272B (128 halves + pad)
#define SMEM1 (2 * STGA + 3 * STGA)    // 92160
#define SMEM2 (STGH + 2 * STGH)        // 104448

// ---------------------------------------------------------------------------
__device__ __forceinline__ uint32_t smem_u32(const void* p) {
    uint32_t a;
    asm("{ .reg .u64 t; cvta.to.shared.u64 t, %1; cvt.u32.u64 %0, t; }" : "=r"(a) : "l"(p));
    return a;
}
__device__ __forceinline__ unsigned h2u(__half2 h) {
    unsigned u; memcpy(&u, &h, 4); return u;
}
__device__ __forceinline__ void cp16(uint32_t dst, const void* src) {
    asm volatile("cp.async.cg.shared.global [%0], [%1], 16;" :: "r"(dst), "l"(src));
}
__device__ __forceinline__ void commit_group() {
    asm volatile("cp.async.commit_group;" ::: "memory");
}
__device__ __forceinline__ void sts128(uint32_t a, unsigned u0, unsigned u1, unsigned u2, unsigned u3) {
    asm volatile("st.shared.v4.b32 [%0], {%1,%2,%3,%4};" :: "r"(a), "r"(u0), "r"(u1), "r"(u2), "r"(u3));
}
__device__ __forceinline__ void ldsm_x4(unsigned r[4], uint32_t addr) {
    asm volatile("ldmatrix.sync.aligned.m8n8.x4.shared.b16 {%0,%1,%2,%3}, [%4];"
                 : "=r"(r[0]), "=r"(r[1]), "=r"(r[2]), "=r"(r[3]) : "r"(addr));
}
__device__ __forceinline__ void mma16816(float c[4], const unsigned a[4], unsigned b0, unsigned b1) {
    asm volatile(
        "mma.sync.aligned.m16n8k16.row.col.f32.f16.f16.f32 "
        "{%0,%1,%2,%3}, {%4,%5,%6,%7}, {%8,%9}, {%0,%1,%2,%3};"
        : "+f"(c[0]), "+f"(c[1]), "+f"(c[2]), "+f"(c[3])
        : "r"(a[0]), "r"(a[1]), "r"(a[2]), "r"(a[3]), "r"(b0), "r"(b1));
}

// ---------------------------------------------------------------------------
// Pre-convert params to fp16 concatenated layouts (rn rounding).
// ALPHA=2 is folded into Bcat (exact in fp16: exponent shift only).
// ---------------------------------------------------------------------------
__global__ void preconv_kernel(const float* __restrict__ A_exp,
                               const float* __restrict__ B_exp,
                               const float* __restrict__ A_gen,
                               const float* __restrict__ B_gen)
{
    int idx = blockIdx.x * blockDim.x + threadIdx.x;
    const int NA = 8 * 128 * Dsz / 2;
    if (idx < NA) {
        int p = idx * 2;
        int e = p / (128 * Dsz);
        int r = p % (128 * Dsz);
        int n = r / Dsz, k = r % Dsz;
        float f0, f1;
        if (n < Rsz) {
            const float* s = A_exp + ((size_t)e * Rsz + n) * Dsz + k;
            f0 = s[0]; f1 = s[1];
        } else {
            const float* s = A_gen + (size_t)(n - Rsz) * Dsz + k;
            f0 = s[0]; f1 = s[1];
        }
        *reinterpret_cast<__half2*>(&g_Acat[p]) = __floats2half2_rn(f0, f1);

        int e2 = p / (Dsz * 128);
        int r2 = p % (Dsz * 128);
        int d = r2 / 128, k2 = r2 % 128;
        float g0, g1;
        if (k2 < Rsz) {
            const float* s = B_exp + ((size_t)e2 * Dsz + d) * Rsz + k2;
            g0 = s[0]; g1 = s[1];
        } else {
            const float* s = B_gen + (size_t)d * Rsz + (k2 - Rsz);
            g0 = s[0]; g1 = s[1];
        }
        *reinterpret_cast<__half2*>(&g_Bcat[p]) = __floats2half2_rn(2.0f * g0, 2.0f * g1);
    }
}

// ---------------------------------------------------------------------------
// GEMM1: H[b] (4096x128) = x[b] @ Acat[b]^T, fp16 mma, output fp16 to g_H.
// grid (32, 31), 256 thr (8 warps 4Mx2N, warp tile 32x64). K-stage 64, KT=20.
// x producer decoupled: LDG+cvt one full iteration before its STS.
// (byte-identical to R7 — proven local optimum)
// ---------------------------------------------------------------------------
__global__ __launch_bounds__(256, 2) void gemm1_fp16(
    const float* __restrict__ x,
    const int*   __restrict__ label)
{
    extern __shared__ char smem[];
    const int b   = blockIdx.y;
    const int m0  = blockIdx.x * 128;
    const int e   = __ldg(&label[b]);
    const int tid = threadIdx.x;
    const int warp = tid >> 5, lane = tid & 31;
    const int wm = warp & 3, wn = warp >> 2;
    const int lg = lane >> 2, lc = lane & 3;

    uint32_t sX = smem_u32(smem);                 // x ring: 2 stages
    uint32_t sA = sX + 2 * STGA;                  // Acat ring: 3 stages

    const char* xb = (const char*)(x + ((size_t)b * Ssz + m0) * Dsz);
    const char* Ab = (const char*)g_Acat + (size_t)e * 128 * Dsz * 2;

    uint32_t aoff[2], boff[4];
#pragma unroll
    for (int i = 0; i < 2; i++)
        aoff[i] = (uint32_t)((wm * 32 + i * 16 + (lane & 15)) * 144 + ((lane >> 4) << 4));
#pragma unroll
    for (int jp = 0; jp < 4; jp++)
        boff[jp] = (uint32_t)((wn * 64 + jp * 16 + (lane & 7) + ((lane >> 4) << 3)) * 144
                              + (((lane >> 3) & 1) << 4));

    auto cp_A = [&](int j) {
        uint32_t dst = sA + (j % 3) * STGA;
        const char* base = Ab + (size_t)j * 128;
#pragma unroll
        for (int i = 0; i < 4; i++) {
            int cid = tid + i * 256;
            int row = cid >> 3, g = cid & 7;
            cp16(dst + row * 144 + g * 16, base + (size_t)row * (Dsz * 2) + g * 16);
        }
        commit_group();
    };

    unsigned xu[16];
    auto ldg_x = [&](int j) {
#pragma unroll
        for (int q = 0; q < 4; q++) {
            int cid = tid + q * 256;
            int row = cid >> 3, gp = cid & 7;
            const float4* src = (const float4*)(xb + (size_t)row * (Dsz * 4) + j * 256 + gp * 32);
            float4 a = __ldg(src);
            float4 c = __ldg(src + 1);
            xu[q*4+0] = h2u(__floats2half2_rn(a.x, a.y));
            xu[q*4+1] = h2u(__floats2half2_rn(a.z, a.w));
            xu[q*4+2] = h2u(__floats2half2_rn(c.x, c.y));
            xu[q*4+3] = h2u(__floats2half2_rn(c.z, c.w));
        }
    };
    auto sts_x = [&](int j) {
        uint32_t dst = sX + (j & 1) * STGA;
#pragma unroll
        for (int q = 0; q < 4; q++) {
            int cid = tid + q * 256;
            int row = cid >> 3, gp = cid & 7;
            sts128(dst + row * 144 + gp * 16, xu[q*4+0], xu[q*4+1], xu[q*4+2], xu[q*4+3]);
        }
    };

    cp_A(0);
    cp_A(1);
    ldg_x(0);
    sts_x(0);
    ldg_x(1);
    asm volatile("cp.async.wait_group 1;" ::: "memory");
    __syncthreads();

    float acc[2][8][4] = {};

    const int KT = Dsz / 64;    // 20
#pragma unroll 1
    for (int kt = 0; kt < KT; kt++) {
        if (kt + 2 < KT) cp_A(kt + 2);
        else             commit_group();

        uint32_t aS = sX + (kt & 1) * STGA;
        uint32_t bS = sA + (kt % 3) * STGA;

#pragma unroll
        for (int kk = 0; kk < 4; kk++) {
            unsigned af[2][4], bf[4][4];
            uint32_t kb = kk * 32;
#pragma unroll
            for (int i = 0; i < 2; i++) ldsm_x4(af[i], aS + aoff[i] + kb);
#pragma unroll
            for (int jp = 0; jp < 4; jp++) ldsm_x4(bf[jp], bS + boff[jp] + kb);
#pragma unroll
            for (int i = 0; i < 2; i++)
#pragma unroll
                for (int jp = 0; jp < 4; jp++) {
                    mma16816(acc[i][2*jp],   af[i], bf[jp][0], bf[jp][1]);
                    mma16816(acc[i][2*jp+1], af[i], bf[jp][2], bf[jp][3]);
                }
        }

        if (kt + 1 < KT) sts_x(kt + 1);
        if (kt + 2 < KT) ldg_x(kt + 2);

        asm volatile("cp.async.wait_group 1;" ::: "memory");
        __syncthreads();
    }

    __half* Hb = g_H + ((size_t)b * Ssz + m0) * 128;
#pragma unroll
    for (int i = 0; i < 2; i++) {
        int r = wm * 32 + i * 16 + lg;
#pragma unroll
        for (int j = 0; j < 8; j++) {
            int c = wn * 64 + j * 8 + lc * 2;
            *reinterpret_cast<__half2*>(Hb + (size_t)r * 128 + c) =
                __floats2half2_rn(acc[i][j][0], acc[i][j][1]);
            *reinterpret_cast<__half2*>(Hb + (size_t)(r + 8) * 128 + c) =
                __floats2half2_rn(acc[i][j][2], acc[i][j][3]);
        }
    }
}

// ---------------------------------------------------------------------------
// GEMM2: out[b] (4096x1280) = H[b] @ Bcat[b]^T  (ALPHA already folded into Bcat).
// grid (32, 2, 32), 256 thr. Each CTA handles 5 of the 10 n-tiles of its
// m-tile (n-split halves the serial loop, doubles CTA count -> ~99% wave fill).
// Per-warp per-nt work identical to R7. b==31 CTAs zero their half-slice.
// ---------------------------------------------------------------------------
__global__ __launch_bounds__(256, 2) void gemm2_fp16(
    const int* __restrict__ label,
    float*     __restrict__ out)
{
    extern __shared__ char smem[];
    const int b   = blockIdx.z;
    const int ny  = blockIdx.y;          // n-half: tiles [ny*5, ny*5+5)
    const int m0  = blockIdx.x * 128;
    const int tid = threadIdx.x;
    const int nt0 = ny * 5;

    float* ob = out + ((size_t)b * Ssz + m0) * Dsz;

    if (b == Bsz - 1) {
        float4 z = make_float4(0.f, 0.f, 0.f, 0.f);
        float* obh = ob + ny * 640;
#pragma unroll 4
        for (int i = 0; i < 80; i++) {
            int v = tid + i * 256;       // 20480 float4 = 128 rows x 160
            int row = v / 160, c4 = v % 160;
            __stcs((float4*)(obh + (size_t)row * Dsz + c4 * 4), z);
        }
        return;
    }

    const int e = __ldg(&label[b]);
    const int warp = tid >> 5, lane = tid & 31;
    const int wm = warp & 3, wn = warp >> 2;
    const int lg = lane >> 2, lc = lane & 3;

    uint32_t sH = smem_u32(smem);
    uint32_t sB = sH + STGH;

    uint32_t aoff[2], boff[4];
#pragma unroll
    for (int i = 0; i < 2; i++)
        aoff[i] = (uint32_t)((wm * 32 + i * 16 + (lane & 15)) * 272 + ((lane >> 4) << 4));
#pragma unroll
    for (int jp = 0; jp < 4; jp++)
        boff[jp] = (uint32_t)((wn * 64 + jp * 16 + (lane & 7) + ((lane >> 4) << 3)) * 272
                              + (((lane >> 3) & 1) << 4));

    // H tile load (once)
    {
        const char* base = (const char*)g_H + ((size_t)b * Ssz + m0) * 256;
#pragma unroll
        for (int i = 0; i < 8; i++) {
            int cid = tid + i * 256;
            int row = cid >> 4, g = cid & 15;
            cp16(sH + row * 272 + g * 16, base + (size_t)row * 256 + g * 16);
        }
        commit_group();
    }

    auto cp_B = [&](int nt) {
        uint32_t dst = sB + (nt & 1) * STGH;
        const char* base = (const char*)g_Bcat + ((size_t)e * Dsz + nt * 128) * 256;
#pragma unroll
        for (int i = 0; i < 8; i++) {
            int cid = tid + i * 256;
            int row = cid >> 4, g = cid & 15;
            cp16(dst + row * 272 + g * 16, base + (size_t)row * 256 + g * 16);
        }
        commit_group();
    };

    cp_B(nt0);
    cp_B(nt0 + 1);
    asm volatile("cp.async.wait_group 1;" ::: "memory");   // H + B(nt0) ready
    __syncthreads();

#pragma unroll 1
    for (int t = 0; t < 5; t++) {
        const int nt = nt0 + t;
        float acc[2][8][4] = {};
        uint32_t bS = sB + (nt & 1) * STGH;

#pragma unroll
        for (int kk = 0; kk < 8; kk++) {
            unsigned af[2][4], bf[4][4];
            uint32_t kb = kk * 32;
#pragma unroll
            for (int i = 0; i < 2; i++) ldsm_x4(af[i], sH + aoff[i] + kb);
#pragma unroll
            for (int jp = 0; jp < 4; jp++) ldsm_x4(bf[jp], bS + boff[jp] + kb);
#pragma unroll
            for (int i = 0; i < 2; i++)
#pragma unroll
                for (int jp = 0; jp < 4; jp++) {
                    mma16816(acc[i][2*jp],   af[i], bf[jp][0], bf[jp][1]);
                    mma16816(acc[i][2*jp+1], af[i], bf[jp][2], bf[jp][3]);
                }
        }

        __syncthreads();                      // all warps done reading slot nt&1
        if (t + 2 < 5) cp_B(nt + 2);          // refill freed slot, overlaps epilogue
        else           commit_group();

        // epilogue for this n-tile (ALPHA pre-folded; hides B transfer)
        int n0 = nt * 128;
#pragma unroll
        for (int i = 0; i < 2; i++) {
            int r = wm * 32 + i * 16 + lg;
#pragma unroll
            for (int j = 0; j < 8; j++) {
                int c = n0 + wn * 64 + j * 8 + lc * 2;
                __stcs((float2*)&ob[(size_t)r * Dsz + c],
                       make_float2(acc[i][j][0], acc[i][j][1]));
                __stcs((float2*)&ob[(size_t)(r + 8) * Dsz + c],
                       make_float2(acc[i][j][2], acc[i][j][3]));
            }
        }

        asm volatile("cp.async.wait_group 1;" ::: "memory");   // B(nt+1) complete
        __syncthreads();
    }
}

// ---------------------------------------------------------------------------
extern "C" void kernel_launch(void* const* d_in, const int* in_sizes, int n_in,
                              void* d_out, int out_size)
{
    const float* x     = (const float*)d_in[0];
    // d_in[1] = weight : unused by the reference
    const float* A_exp = (const float*)d_in[2];
    const float* B_exp = (const float*)d_in[3];
    const float* A_gen = (const float*)d_in[4];
    const float* B_gen = (const float*)d_in[5];
    const int*   label = (const int*)d_in[6];
    float* out = (float*)d_out;

    cudaFuncSetAttribute(gemm1_fp16, cudaFuncAttributeMaxDynamicSharedMemorySize, SMEM1);
    cudaFuncSetAttribute(gemm2_fp16, cudaFuncAttributeMaxDynamicSharedMemorySize, SMEM2);

    preconv_kernel<<<(8 * 128 * Dsz / 2 + 255) / 256, 256>>>(A_exp, B_exp, A_gen, B_gen);
    gemm1_fp16<<<dim3(Ssz / 128, Bsz - 1), 256, SMEM1>>>(x, label);
    gemm2_fp16<<<dim3(Ssz / 128, 2, Bsz), 256, SMEM2>>>(label, out);
}

// round 13
// speedup vs baseline: 1.3087x; 1.0835x over previous
#include <cuda_runtime.h>
#include <cuda_fp16.h>
#include <cstdint>
#include <cstring>

#define Bsz 32
#define Ssz 4096
#define Dsz 1280
#define Rsz 64

// fp16 scratch: concatenated pre-rounded params + intermediate H
__device__ __half g_Acat[8 * 128 * Dsz];          // [e][n(128)][k(1280)]
__device__ __half g_Bcat[8 * Dsz * 128];          // [e][d(1280)][k(128)], pre-scaled by ALPHA
__device__ __half g_H[31u * Ssz * 128];           // [b][m][k(128)]

#define XSTG 36864          // 128 rows x 288B (64 fp32 + 8 pad words) — conflict-free frag reads
#define ASTG 18432          // 128 rows x 144B (64 halves + pad)
#define STGH 34816          // 128 rows x 272B (128 halves + pad)
#define SMEM1 (2 * XSTG + 2 * ASTG)    // 110592
#define SMEM2 (STGH + 2 * STGH)        // 104448

// ---------------------------------------------------------------------------
__device__ __forceinline__ uint32_t smem_u32(const void* p) {
    uint32_t a;
    asm("{ .reg .u64 t; cvta.to.shared.u64 t, %1; cvt.u32.u64 %0, t; }" : "=r"(a) : "l"(p));
    return a;
}
__device__ __forceinline__ unsigned h2u(__half2 h) {
    unsigned u; memcpy(&u, &h, 4); return u;
}
__device__ __forceinline__ void cp16(uint32_t dst, const void* src) {
    asm volatile("cp.async.cg.shared.global [%0], [%1], 16;" :: "r"(dst), "l"(src));
}
__device__ __forceinline__ void commit_group() {
    asm volatile("cp.async.commit_group;" ::: "memory");
}
__device__ __forceinline__ float2 lds64(uint32_t a) {
    float2 v;
    asm("ld.shared.v2.f32 {%0,%1}, [%2];" : "=f"(v.x), "=f"(v.y) : "r"(a));
    return v;
}
__device__ __forceinline__ void ldsm_x4(unsigned r[4], uint32_t addr) {
    asm volatile("ldmatrix.sync.aligned.m8n8.x4.shared.b16 {%0,%1,%2,%3}, [%4];"
                 : "=r"(r[0]), "=r"(r[1]), "=r"(r[2]), "=r"(r[3]) : "r"(addr));
}
__device__ __forceinline__ void mma16816(float c[4], const unsigned a[4], unsigned b0, unsigned b1) {
    asm volatile(
        "mma.sync.aligned.m16n8k16.row.col.f32.f16.f16.f32 "
        "{%0,%1,%2,%3}, {%4,%5,%6,%7}, {%8,%9}, {%0,%1,%2,%3};"
        : "+f"(c[0]), "+f"(c[1]), "+f"(c[2]), "+f"(c[3])
        : "r"(a[0]), "r"(a[1]), "r"(a[2]), "r"(a[3]), "r"(b0), "r"(b1));
}

// ---------------------------------------------------------------------------
// Pre-convert params to fp16 concatenated layouts (rn rounding).
// ALPHA=2 folded into Bcat (exact in fp16: exponent shift only).
// ---------------------------------------------------------------------------
__global__ void preconv_kernel(const float* __restrict__ A_exp,
                               const float* __restrict__ B_exp,
                               const float* __restrict__ A_gen,
                               const float* __restrict__ B_gen)
{
    int idx = blockIdx.x * blockDim.x + threadIdx.x;
    const int NA = 8 * 128 * Dsz / 2;
    if (idx < NA) {
        int p = idx * 2;
        int e = p / (128 * Dsz);
        int r = p % (128 * Dsz);
        int n = r / Dsz, k = r % Dsz;
        float f0, f1;
        if (n < Rsz) {
            const float* s = A_exp + ((size_t)e * Rsz + n) * Dsz + k;
            f0 = s[0]; f1 = s[1];
        } else {
            const float* s = A_gen + (size_t)(n - Rsz) * Dsz + k;
            f0 = s[0]; f1 = s[1];
        }
        *reinterpret_cast<__half2*>(&g_Acat[p]) = __floats2half2_rn(f0, f1);

        int e2 = p / (Dsz * 128);
        int r2 = p % (Dsz * 128);
        int d = r2 / 128, k2 = r2 % 128;
        float g0, g1;
        if (k2 < Rsz) {
            const float* s = B_exp + ((size_t)e2 * Dsz + d) * Rsz + k2;
            g0 = s[0]; g1 = s[1];
        } else {
            const float* s = B_gen + (size_t)d * Rsz + (k2 - Rsz);
            g0 = s[0]; g1 = s[1];
        }
        *reinterpret_cast<__half2*>(&g_Bcat[p]) = __floats2half2_rn(2.0f * g0, 2.0f * g1);
    }
}

// ---------------------------------------------------------------------------
// GEMM1: H[b] (4096x128) = x[b] @ Acat[b]^T, fp16 mma, output fp16 to g_H.
// grid (32, 31), 256 thr (8 warps 4Mx2N, warp tile 32x64). K-stage 64, KT=20.
// x staged as RAW fp32 via cp.async (2-stage ring, 288B rows); A-fragments
// built in-loop via ld.shared.v2.f32 + cvt (no register-staged producer).
// ---------------------------------------------------------------------------
__global__ __launch_bounds__(256, 2) void gemm1_fp16(
    const float* __restrict__ x,
    const int*   __restrict__ label)
{
    extern __shared__ char smem[];
    const int b   = blockIdx.y;
    const int m0  = blockIdx.x * 128;
    const int e   = __ldg(&label[b]);
    const int tid = threadIdx.x;
    const int warp = tid >> 5, lane = tid & 31;
    const int wm = warp & 3, wn = warp >> 2;
    const int lg = lane >> 2, lc = lane & 3;

    uint32_t sX = smem_u32(smem);                 // x ring: 2 stages, fp32
    uint32_t sA = sX + 2 * XSTG;                  // Acat ring: 2 stages, fp16

    const char* xb = (const char*)(x + ((size_t)b * Ssz + m0) * Dsz);
    const char* Ab = (const char*)g_Acat + (size_t)e * 128 * Dsz * 2;

    // x fragment LDS base per m-sub (stride 288B; lc*2 fp32 = lc*8 bytes)
    uint32_t xoff[2];
#pragma unroll
    for (int i = 0; i < 2; i++)
        xoff[i] = (uint32_t)((wm * 32 + i * 16 + lg) * 288 + lc * 8);

    // A (param) ldmatrix offsets (stride 144)
    uint32_t boff[4];
#pragma unroll
    for (int jp = 0; jp < 4; jp++)
        boff[jp] = (uint32_t)((wn * 64 + jp * 16 + (lane & 7) + ((lane >> 4) << 3)) * 144
                              + (((lane >> 3) & 1) << 4));

    // One stage = x k-slice (128 rows x 256B fp32) + A k-slice (128 rows x 128B fp16)
    auto stage = [&](int j) {
        uint32_t dX = sX + (j & 1) * XSTG;
        uint32_t dA = sA + (j & 1) * ASTG;
#pragma unroll
        for (int i = 0; i < 8; i++) {             // 2048 x-chunks
            int cid = tid + i * 256;
            int row = cid >> 4, g = cid & 15;
            cp16(dX + row * 288 + g * 16, xb + (size_t)row * (Dsz * 4) + j * 256 + g * 16);
        }
#pragma unroll
        for (int i = 0; i < 4; i++) {             // 1024 A-chunks
            int cid = tid + i * 256;
            int row = cid >> 3, g = cid & 7;
            cp16(dA + row * 144 + g * 16, Ab + (size_t)row * (Dsz * 2) + j * 128 + g * 16);
        }
        commit_group();
    };

    stage(0);
    stage(1);
    asm volatile("cp.async.wait_group 1;" ::: "memory");   // stage 0 complete
    __syncthreads();

    float acc[2][8][4] = {};

    const int KT = Dsz / 64;    // 20
#pragma unroll 1
    for (int kt = 0; kt < KT; kt++) {
        uint32_t xS = sX + (kt & 1) * XSTG;
        uint32_t aS = sA + (kt & 1) * ASTG;

#pragma unroll
        for (int kk = 0; kk < 4; kk++) {
            unsigned af[2][4], bf[4][4];
#pragma unroll
            for (int i = 0; i < 2; i++) {
                uint32_t base = xS + xoff[i] + kk * 64;
                float2 p0 = lds64(base);
                float2 p1 = lds64(base + 8 * 288);
                float2 p2 = lds64(base + 32);
                float2 p3 = lds64(base + 8 * 288 + 32);
                af[i][0] = h2u(__floats2half2_rn(p0.x, p0.y));
                af[i][1] = h2u(__floats2half2_rn(p1.x, p1.y));
                af[i][2] = h2u(__floats2half2_rn(p2.x, p2.y));
                af[i][3] = h2u(__floats2half2_rn(p3.x, p3.y));
            }
#pragma unroll
            for (int jp = 0; jp < 4; jp++) ldsm_x4(bf[jp], aS + boff[jp] + kk * 32);
#pragma unroll
            for (int i = 0; i < 2; i++)
#pragma unroll
                for (int jp = 0; jp < 4; jp++) {
                    mma16816(acc[i][2*jp],   af[i], bf[jp][0], bf[jp][1]);
                    mma16816(acc[i][2*jp+1], af[i], bf[jp][2], bf[jp][3]);
                }
        }

        __syncthreads();                          // all warps done with slot kt&1
        if (kt + 2 < KT) stage(kt + 2);           // refill freed slot
        else             commit_group();
        asm volatile("cp.async.wait_group 1;" ::: "memory");  // stage kt+1 ready
        __syncthreads();
    }

    // epilogue: H (fp16) -> global
    __half* Hb = g_H + ((size_t)b * Ssz + m0) * 128;
#pragma unroll
    for (int i = 0; i < 2; i++) {
        int r = wm * 32 + i * 16 + lg;
#pragma unroll
        for (int j = 0; j < 8; j++) {
            int c = wn * 64 + j * 8 + lc * 2;
            *reinterpret_cast<__half2*>(Hb + (size_t)r * 128 + c) =
                __floats2half2_rn(acc[i][j][0], acc[i][j][1]);
            *reinterpret_cast<__half2*>(Hb + (size_t)(r + 8) * 128 + c) =
                __floats2half2_rn(acc[i][j][2], acc[i][j][3]);
        }
    }
}

// ---------------------------------------------------------------------------
// GEMM2: out[b] (4096x1280) = H[b] @ Bcat[b]^T  (ALPHA folded into Bcat).
// grid (32, 2, 32), 256 thr; each CTA does 5 of 10 n-tiles (R12, == R7 perf).
// b==31 CTAs zero their half-slice.
// ---------------------------------------------------------------------------
__global__ __launch_bounds__(256, 2) void gemm2_fp16(
    const int* __restrict__ label,
    float*     __restrict__ out)
{
    extern __shared__ char smem[];
    const int b   = blockIdx.z;
    const int ny  = blockIdx.y;
    const int m0  = blockIdx.x * 128;
    const int tid = threadIdx.x;
    const int nt0 = ny * 5;

    float* ob = out + ((size_t)b * Ssz + m0) * Dsz;

    if (b == Bsz - 1) {
        float4 z = make_float4(0.f, 0.f, 0.f, 0.f);
        float* obh = ob + ny * 640;
#pragma unroll 4
        for (int i = 0; i < 80; i++) {
            int v = tid + i * 256;
            int row = v / 160, c4 = v % 160;
            __stcs((float4*)(obh + (size_t)row * Dsz + c4 * 4), z);
        }
        return;
    }

    const int e = __ldg(&label[b]);
    const int warp = tid >> 5, lane = tid & 31;
    const int wm = warp & 3, wn = warp >> 2;
    const int lg = lane >> 2, lc = lane & 3;

    uint32_t sH = smem_u32(smem);
    uint32_t sB = sH + STGH;

    uint32_t aoff[2], boff[4];
#pragma unroll
    for (int i = 0; i < 2; i++)
        aoff[i] = (uint32_t)((wm * 32 + i * 16 + (lane & 15)) * 272 + ((lane >> 4) << 4));
#pragma unroll
    for (int jp = 0; jp < 4; jp++)
        boff[jp] = (uint32_t)((wn * 64 + jp * 16 + (lane & 7) + ((lane >> 4) << 3)) * 272
                              + (((lane >> 3) & 1) << 4));

    // H tile load (once)
    {
        const char* base = (const char*)g_H + ((size_t)b * Ssz + m0) * 256;
#pragma unroll
        for (int i = 0; i < 8; i++) {
            int cid = tid + i * 256;
            int row = cid >> 4, g = cid & 15;
            cp16(sH + row * 272 + g * 16, base + (size_t)row * 256 + g * 16);
        }
        commit_group();
    }

    auto cp_B = [&](int nt) {
        uint32_t dst = sB + (nt & 1) * STGH;
        const char* base = (const char*)g_Bcat + ((size_t)e * Dsz + nt * 128) * 256;
#pragma unroll
        for (int i = 0; i < 8; i++) {
            int cid = tid + i * 256;
            int row = cid >> 4, g = cid & 15;
            cp16(dst + row * 272 + g * 16, base + (size_t)row * 256 + g * 16);
        }
        commit_group();
    };

    cp_B(nt0);
    cp_B(nt0 + 1);
    asm volatile("cp.async.wait_group 1;" ::: "memory");   // H + B(nt0) ready
    __syncthreads();

#pragma unroll 1
    for (int t = 0; t < 5; t++) {
        const int nt = nt0 + t;
        float acc[2][8][4] = {};
        uint32_t bS = sB + (nt & 1) * STGH;

#pragma unroll
        for (int kk = 0; kk < 8; kk++) {
            unsigned af[2][4], bf[4][4];
            uint32_t kb = kk * 32;
#pragma unroll
            for (int i = 0; i < 2; i++) ldsm_x4(af[i], sH + aoff[i] + kb);
#pragma unroll
            for (int jp = 0; jp < 4; jp++) ldsm_x4(bf[jp], bS + boff[jp] + kb);
#pragma unroll
            for (int i = 0; i < 2; i++)
#pragma unroll
                for (int jp = 0; jp < 4; jp++) {
                    mma16816(acc[i][2*jp],   af[i], bf[jp][0], bf[jp][1]);
                    mma16816(acc[i][2*jp+1], af[i], bf[jp][2], bf[jp][3]);
                }
        }

        __syncthreads();
        if (t + 2 < 5) cp_B(nt + 2);
        else           commit_group();

        int n0 = nt * 128;
#pragma unroll
        for (int i = 0; i < 2; i++) {
            int r = wm * 32 + i * 16 + lg;
#pragma unroll
            for (int j = 0; j < 8; j++) {
                int c = n0 + wn * 64 + j * 8 + lc * 2;
                __stcs((float2*)&ob[(size_t)r * Dsz + c],
                       make_float2(acc[i][j][0], acc[i][j][1]));
                __stcs((float2*)&ob[(size_t)(r + 8) * Dsz + c],
                       make_float2(acc[i][j][2], acc[i][j][3]));
            }
        }

        asm volatile("cp.async.wait_group 1;" ::: "memory");
        __syncthreads();
    }
}

// ---------------------------------------------------------------------------
extern "C" void kernel_launch(void* const* d_in, const int* in_sizes, int n_in,
                              void* d_out, int out_size)
{
    const float* x     = (const float*)d_in[0];
    // d_in[1] = weight : unused by the reference
    const float* A_exp = (const float*)d_in[2];
    const float* B_exp = (const float*)d_in[3];
    const float* A_gen = (const float*)d_in[4];
    const float* B_gen = (const float*)d_in[5];
    const int*   label = (const int*)d_in[6];
    float* out = (float*)d_out;

    cudaFuncSetAttribute(gemm1_fp16, cudaFuncAttributeMaxDynamicSharedMemorySize, SMEM1);
    cudaFuncSetAttribute(gemm2_fp16, cudaFuncAttributeMaxDynamicSharedMemorySize, SMEM2);

    preconv_kernel<<<(8 * 128 * Dsz / 2 + 255) / 256, 256>>>(A_exp, B_exp, A_gen, B_gen);
    gemm1_fp16<<<dim3(Ssz / 128, Bsz - 1), 256, SMEM1>>>(x, label);
    gemm2_fp16<<<dim3(Ssz / 128, 2, Bsz), 256, SMEM2>>>(label, out);
}

// round 14
// speedup vs baseline: 1.3664x; 1.0441x over previous
#include <cuda_runtime.h>
#include <cuda_fp16.h>
#include <cstdint>
#include <cstring>

#define Bsz 32
#define Ssz 4096
#define Dsz 1280
#define Rsz 64

// fp16 scratch: concatenated pre-rounded params + intermediate H
__device__ __half g_Acat[8 * 128 * Dsz];          // [e][n(128)][k(1280)]
__device__ __half g_Bcat[8 * Dsz * 128];          // [e][d(1280)][k(128)], pre-scaled by ALPHA
__device__ __half g_H[31u * Ssz * 128];           // [b][m][k(128)]

#define XSTG 36864          // 128 rows x 288B (64 fp32 + 8 pad words)
#define ASTG 18432          // 128 rows x 144B (64 halves + pad)
#define STGH 34816          // 128 rows x 272B (128 halves + pad)
#define SMEM1 (2 * XSTG + 2 * ASTG)    // 110592
#define SMEM2 (STGH + 2 * STGH)        // 104448

// ---------------------------------------------------------------------------
__device__ __forceinline__ uint32_t smem_u32(const void* p) {
    uint32_t a;
    asm("{ .reg .u64 t; cvta.to.shared.u64 t, %1; cvt.u32.u64 %0, t; }" : "=r"(a) : "l"(p));
    return a;
}
__device__ __forceinline__ unsigned h2u(__half2 h) {
    unsigned u; memcpy(&u, &h, 4); return u;
}
__device__ __forceinline__ void cp16(uint32_t dst, const void* src) {
    asm volatile("cp.async.cg.shared.global [%0], [%1], 16;" :: "r"(dst), "l"(src));
}
__device__ __forceinline__ void commit_group() {
    asm volatile("cp.async.commit_group;" ::: "memory");
}
__device__ __forceinline__ float2 lds64(uint32_t a) {
    float2 v;
    asm("ld.shared.v2.f32 {%0,%1}, [%2];" : "=f"(v.x), "=f"(v.y) : "r"(a));
    return v;
}
__device__ __forceinline__ void ldsm_x4(unsigned r[4], uint32_t addr) {
    asm volatile("ldmatrix.sync.aligned.m8n8.x4.shared.b16 {%0,%1,%2,%3}, [%4];"
                 : "=r"(r[0]), "=r"(r[1]), "=r"(r[2]), "=r"(r[3]) : "r"(addr));
}
__device__ __forceinline__ void mma16816(float c[4], const unsigned a[4], unsigned b0, unsigned b1) {
    asm volatile(
        "mma.sync.aligned.m16n8k16.row.col.f32.f16.f16.f32 "
        "{%0,%1,%2,%3}, {%4,%5,%6,%7}, {%8,%9}, {%0,%1,%2,%3};"
        : "+f"(c[0]), "+f"(c[1]), "+f"(c[2]), "+f"(c[3])
        : "r"(a[0]), "r"(a[1]), "r"(a[2]), "r"(a[3]), "r"(b0), "r"(b1));
}

// ---------------------------------------------------------------------------
// Pre-convert params to fp16 concatenated layouts (rn rounding).
// ALPHA=2 folded into Bcat (exact in fp16: exponent shift only).
// ---------------------------------------------------------------------------
__global__ void preconv_kernel(const float* __restrict__ A_exp,
                               const float* __restrict__ B_exp,
                               const float* __restrict__ A_gen,
                               const float* __restrict__ B_gen)
{
    int idx = blockIdx.x * blockDim.x + threadIdx.x;
    const int NA = 8 * 128 * Dsz / 2;
    if (idx < NA) {
        int p = idx * 2;
        int e = p / (128 * Dsz);
        int r = p % (128 * Dsz);
        int n = r / Dsz, k = r % Dsz;
        float f0, f1;
        if (n < Rsz) {
            const float* s = A_exp + ((size_t)e * Rsz + n) * Dsz + k;
            f0 = s[0]; f1 = s[1];
        } else {
            const float* s = A_gen + (size_t)(n - Rsz) * Dsz + k;
            f0 = s[0]; f1 = s[1];
        }
        *reinterpret_cast<__half2*>(&g_Acat[p]) = __floats2half2_rn(f0, f1);

        int e2 = p / (Dsz * 128);
        int r2 = p % (Dsz * 128);
        int d = r2 / 128, k2 = r2 % 128;
        float g0, g1;
        if (k2 < Rsz) {
            const float* s = B_exp + ((size_t)e2 * Dsz + d) * Rsz + k2;
            g0 = s[0]; g1 = s[1];
        } else {
            const float* s = B_gen + (size_t)d * Rsz + (k2 - Rsz);
            g0 = s[0]; g1 = s[1];
        }
        *reinterpret_cast<__half2*>(&g_Bcat[p]) = __floats2half2_rn(2.0f * g0, 2.0f * g1);
    }
}

// ---------------------------------------------------------------------------
// GEMM1: H[b] (4096x128) = x[b] @ Acat[b]^T  (R13 — frozen, at tensor floor).
// ---------------------------------------------------------------------------
__global__ __launch_bounds__(256, 2) void gemm1_fp16(
    const float* __restrict__ x,
    const int*   __restrict__ label)
{
    extern __shared__ char smem[];
    const int b   = blockIdx.y;
    const int m0  = blockIdx.x * 128;
    const int e   = __ldg(&label[b]);
    const int tid = threadIdx.x;
    const int warp = tid >> 5, lane = tid & 31;
    const int wm = warp & 3, wn = warp >> 2;
    const int lg = lane >> 2, lc = lane & 3;

    uint32_t sX = smem_u32(smem);
    uint32_t sA = sX + 2 * XSTG;

    const char* xb = (const char*)(x + ((size_t)b * Ssz + m0) * Dsz);
    const char* Ab = (const char*)g_Acat + (size_t)e * 128 * Dsz * 2;

    uint32_t xoff[2];
#pragma unroll
    for (int i = 0; i < 2; i++)
        xoff[i] = (uint32_t)((wm * 32 + i * 16 + lg) * 288 + lc * 8);

    uint32_t boff[4];
#pragma unroll
    for (int jp = 0; jp < 4; jp++)
        boff[jp] = (uint32_t)((wn * 64 + jp * 16 + (lane & 7) + ((lane >> 4) << 3)) * 144
                              + (((lane >> 3) & 1) << 4));

    auto stage = [&](int j) {
        uint32_t dX = sX + (j & 1) * XSTG;
        uint32_t dA = sA + (j & 1) * ASTG;
#pragma unroll
        for (int i = 0; i < 8; i++) {
            int cid = tid + i * 256;
            int row = cid >> 4, g = cid & 15;
            cp16(dX + row * 288 + g * 16, xb + (size_t)row * (Dsz * 4) + j * 256 + g * 16);
        }
#pragma unroll
        for (int i = 0; i < 4; i++) {
            int cid = tid + i * 256;
            int row = cid >> 3, g = cid & 7;
            cp16(dA + row * 144 + g * 16, Ab + (size_t)row * (Dsz * 2) + j * 128 + g * 16);
        }
        commit_group();
    };

    stage(0);
    stage(1);
    asm volatile("cp.async.wait_group 1;" ::: "memory");
    __syncthreads();

    float acc[2][8][4] = {};

    const int KT = Dsz / 64;    // 20
#pragma unroll 1
    for (int kt = 0; kt < KT; kt++) {
        uint32_t xS = sX + (kt & 1) * XSTG;
        uint32_t aS = sA + (kt & 1) * ASTG;

#pragma unroll
        for (int kk = 0; kk < 4; kk++) {
            unsigned af[2][4], bf[4][4];
#pragma unroll
            for (int i = 0; i < 2; i++) {
                uint32_t base = xS + xoff[i] + kk * 64;
                float2 p0 = lds64(base);
                float2 p1 = lds64(base + 8 * 288);
                float2 p2 = lds64(base + 32);
                float2 p3 = lds64(base + 8 * 288 + 32);
                af[i][0] = h2u(__floats2half2_rn(p0.x, p0.y));
                af[i][1] = h2u(__floats2half2_rn(p1.x, p1.y));
                af[i][2] = h2u(__floats2half2_rn(p2.x, p2.y));
                af[i][3] = h2u(__floats2half2_rn(p3.x, p3.y));
            }
#pragma unroll
            for (int jp = 0; jp < 4; jp++) ldsm_x4(bf[jp], aS + boff[jp] + kk * 32);
#pragma unroll
            for (int i = 0; i < 2; i++)
#pragma unroll
                for (int jp = 0; jp < 4; jp++) {
                    mma16816(acc[i][2*jp],   af[i], bf[jp][0], bf[jp][1]);
                    mma16816(acc[i][2*jp+1], af[i], bf[jp][2], bf[jp][3]);
                }
        }

        __syncthreads();
        if (kt + 2 < KT) stage(kt + 2);
        else             commit_group();
        asm volatile("cp.async.wait_group 1;" ::: "memory");
        __syncthreads();
    }

    __half* Hb = g_H + ((size_t)b * Ssz + m0) * 128;
#pragma unroll
    for (int i = 0; i < 2; i++) {
        int r = wm * 32 + i * 16 + lg;
#pragma unroll
        for (int j = 0; j < 8; j++) {
            int c = wn * 64 + j * 8 + lc * 2;
            *reinterpret_cast<__half2*>(Hb + (size_t)r * 128 + c) =
                __floats2half2_rn(acc[i][j][0], acc[i][j][1]);
            *reinterpret_cast<__half2*>(Hb + (size_t)(r + 8) * 128 + c) =
                __floats2half2_rn(acc[i][j][2], acc[i][j][3]);
        }
    }
}

// ---------------------------------------------------------------------------
// GEMM2: out[b] (4096x1280) = H[b] @ Bcat[b]^T  (ALPHA folded into Bcat).
// grid (32, 2, 32), 256 thr; each CTA does 5 of 10 n-tiles.
// Epilogue: shfl_xor(1) pairs adjacent j-fragments so each thread emits one
// float4 (64B contiguous per row per instr) — halves store wavefronts.
// ---------------------------------------------------------------------------
__global__ __launch_bounds__(256, 2) void gemm2_fp16(
    const int* __restrict__ label,
    float*     __restrict__ out)
{
    extern __shared__ char smem[];
    const int b   = blockIdx.z;
    const int ny  = blockIdx.y;
    const int m0  = blockIdx.x * 128;
    const int tid = threadIdx.x;
    const int nt0 = ny * 5;

    float* ob = out + ((size_t)b * Ssz + m0) * Dsz;

    if (b == Bsz - 1) {
        float4 z = make_float4(0.f, 0.f, 0.f, 0.f);
        float* obh = ob + ny * 640;
#pragma unroll 4
        for (int i = 0; i < 80; i++) {
            int v = tid + i * 256;
            int row = v / 160, c4 = v % 160;
            __stcs((float4*)(obh + (size_t)row * Dsz + c4 * 4), z);
        }
        return;
    }

    const int e = __ldg(&label[b]);
    const int warp = tid >> 5, lane = tid & 31;
    const int wm = warp & 3, wn = warp >> 2;
    const int lg = lane >> 2, lc = lane & 3;

    uint32_t sH = smem_u32(smem);
    uint32_t sB = sH + STGH;

    uint32_t aoff[2], boff[4];
#pragma unroll
    for (int i = 0; i < 2; i++)
        aoff[i] = (uint32_t)((wm * 32 + i * 16 + (lane & 15)) * 272 + ((lane >> 4) << 4));
#pragma unroll
    for (int jp = 0; jp < 4; jp++)
        boff[jp] = (uint32_t)((wn * 64 + jp * 16 + (lane & 7) + ((lane >> 4) << 3)) * 272
                              + (((lane >> 3) & 1) << 4));

    // H tile load (once)
    {
        const char* base = (const char*)g_H + ((size_t)b * Ssz + m0) * 256;
#pragma unroll
        for (int i = 0; i < 8; i++) {
            int cid = tid + i * 256;
            int row = cid >> 4, g = cid & 15;
            cp16(sH + row * 272 + g * 16, base + (size_t)row * 256 + g * 16);
        }
        commit_group();
    }

    auto cp_B = [&](int nt) {
        uint32_t dst = sB + (nt & 1) * STGH;
        const char* base = (const char*)g_Bcat + ((size_t)e * Dsz + nt * 128) * 256;
#pragma unroll
        for (int i = 0; i < 8; i++) {
            int cid = tid + i * 256;
            int row = cid >> 4, g = cid & 15;
            cp16(dst + row * 272 + g * 16, base + (size_t)row * 256 + g * 16);
        }
        commit_group();
    };

    cp_B(nt0);
    cp_B(nt0 + 1);
    asm volatile("cp.async.wait_group 1;" ::: "memory");   // H + B(nt0) ready
    __syncthreads();

#pragma unroll 1
    for (int t = 0; t < 5; t++) {
        const int nt = nt0 + t;
        float acc[2][8][4] = {};
        uint32_t bS = sB + (nt & 1) * STGH;

#pragma unroll
        for (int kk = 0; kk < 8; kk++) {
            unsigned af[2][4], bf[4][4];
            uint32_t kb = kk * 32;
#pragma unroll
            for (int i = 0; i < 2; i++) ldsm_x4(af[i], sH + aoff[i] + kb);
#pragma unroll
            for (int jp = 0; jp < 4; jp++) ldsm_x4(bf[jp], bS + boff[jp] + kb);
#pragma unroll
            for (int i = 0; i < 2; i++)
#pragma unroll
                for (int jp = 0; jp < 4; jp++) {
                    mma16816(acc[i][2*jp],   af[i], bf[jp][0], bf[jp][1]);
                    mma16816(acc[i][2*jp+1], af[i], bf[jp][2], bf[jp][3]);
                }
        }

        __syncthreads();
        if (t + 2 < 5) cp_B(nt + 2);
        else           commit_group();

        // epilogue: pair j-fragments via shfl, emit float4 (64B/row per instr)
        int n0 = nt * 128;
        const bool odd = (lc & 1);
#pragma unroll
        for (int i = 0; i < 2; i++) {
            int r = wm * 32 + i * 16 + lg;
#pragma unroll
            for (int jp2 = 0; jp2 < 4; jp2++) {
                int j0 = jp2 * 2, j1 = j0 + 1;
#pragma unroll
                for (int h = 0; h < 2; h++) {
                    float a0 = acc[i][j0][h*2], a1 = acc[i][j0][h*2+1];
                    float b0 = acc[i][j1][h*2], b1 = acc[i][j1][h*2+1];
                    // even lanes need partner's j0 pair; odd need partner's j1
                    float s0 = odd ? a0 : b0;
                    float s1 = odd ? a1 : b1;
                    float r0 = __shfl_xor_sync(0xffffffffu, s0, 1);
                    float r1 = __shfl_xor_sync(0xffffffffu, s1, 1);
                    float4 v = odd ? make_float4(r0, r1, b0, b1)
                                   : make_float4(a0, a1, r0, r1);
                    int row = r + h * 8;
                    int c = n0 + wn * 64 + (j0 + (lc & 1)) * 8 + (lc >> 1) * 4;
                    __stcs((float4*)&ob[(size_t)row * Dsz + c], v);
                }
            }
        }

        asm volatile("cp.async.wait_group 1;" ::: "memory");   // B(nt+1) complete
        __syncthreads();
    }
}

// ---------------------------------------------------------------------------
extern "C" void kernel_launch(void* const* d_in, const int* in_sizes, int n_in,
                              void* d_out, int out_size)
{
    const float* x     = (const float*)d_in[0];
    // d_in[1] = weight : unused by the reference
    const float* A_exp = (const float*)d_in[2];
    const float* B_exp = (const float*)d_in[3];
    const float* A_gen = (const float*)d_in[4];
    const float* B_gen = (const float*)d_in[5];
    const int*   label = (const int*)d_in[6];
    float* out = (float*)d_out;

    cudaFuncSetAttribute(gemm1_fp16, cudaFuncAttributeMaxDynamicSharedMemorySize, SMEM1);
    cudaFuncSetAttribute(gemm2_fp16, cudaFuncAttributeMaxDynamicSharedMemorySize, SMEM2);

    preconv_kernel<<<(8 * 128 * Dsz / 2 + 255) / 256, 256>>>(A_exp, B_exp, A_gen, B_gen);
    gemm1_fp16<<<dim3(Ssz / 128, Bsz - 1), 256, SMEM1>>>(x, label);
    gemm2_fp16<<<dim3(Ssz / 128, 2, Bsz), 256, SMEM2>>>(label, out);
}

// round 15
// speedup vs baseline: 1.3825x; 1.0118x over previous
#include <cuda_runtime.h>
#include <cuda_fp16.h>
#include <cstdint>
#include <cstring>

#define Bsz 32
#define Ssz 4096
#define Dsz 1280
#define Rsz 64

// fp16 scratch: concatenated pre-rounded params + intermediate H
__device__ __half g_Acat[8 * 128 * Dsz];          // [e][n(128)][k(1280)]
__device__ __half g_Bcat[8 * Dsz * 128];          // [e][d(1280)][k(128)], pre-scaled by ALPHA
__device__ __half g_H[31u * Ssz * 128];           // [b][m][k(128)]

#define XSTG 36864          // 128 rows x 288B (64 fp32 + 8 pad words)
#define ASTG 18432          // 128 rows x 144B (64 halves + pad)
#define STGH 34816          // 128 rows x 272B (128 halves + pad)
#define SMEM1 (2 * XSTG + 2 * ASTG)    // 110592
#define SMEM2 (STGH + 2 * STGH)        // 104448

// ---------------------------------------------------------------------------
__device__ __forceinline__ uint32_t smem_u32(const void* p) {
    uint32_t a;
    asm("{ .reg .u64 t; cvta.to.shared.u64 t, %1; cvt.u32.u64 %0, t; }" : "=r"(a) : "l"(p));
    return a;
}
__device__ __forceinline__ unsigned h2u(__half2 h) {
    unsigned u; memcpy(&u, &h, 4); return u;
}
__device__ __forceinline__ void cp16(uint32_t dst, const void* src) {
    asm volatile("cp.async.cg.shared.global [%0], [%1], 16;" :: "r"(dst), "l"(src));
}
__device__ __forceinline__ void commit_group() {
    asm volatile("cp.async.commit_group;" ::: "memory");
}
__device__ __forceinline__ float2 lds64(uint32_t a) {
    float2 v;
    asm("ld.shared.v2.f32 {%0,%1}, [%2];" : "=f"(v.x), "=f"(v.y) : "r"(a));
    return v;
}
__device__ __forceinline__ void ldsm_x4(unsigned r[4], uint32_t addr) {
    asm volatile("ldmatrix.sync.aligned.m8n8.x4.shared.b16 {%0,%1,%2,%3}, [%4];"
                 : "=r"(r[0]), "=r"(r[1]), "=r"(r[2]), "=r"(r[3]) : "r"(addr));
}
__device__ __forceinline__ void mma16816(float c[4], const unsigned a[4], unsigned b0, unsigned b1) {
    asm volatile(
        "mma.sync.aligned.m16n8k16.row.col.f32.f16.f16.f32 "
        "{%0,%1,%2,%3}, {%4,%5,%6,%7}, {%8,%9}, {%0,%1,%2,%3};"
        : "+f"(c[0]), "+f"(c[1]), "+f"(c[2]), "+f"(c[3])
        : "r"(a[0]), "r"(a[1]), "r"(a[2]), "r"(a[3]), "r"(b0), "r"(b1));
}

// ---------------------------------------------------------------------------
// Pre-convert params to fp16 concatenated layouts (rn rounding), x2 vectorized.
// ALPHA=2 folded into Bcat (exact in fp16: exponent shift only).
// ---------------------------------------------------------------------------
__global__ void preconv_kernel(const float* __restrict__ A_exp,
                               const float* __restrict__ B_exp,
                               const float* __restrict__ A_gen,
                               const float* __restrict__ B_gen)
{
    int idx = blockIdx.x * blockDim.x + threadIdx.x;     // 4-half group index
    const int NG = 8 * 128 * Dsz / 4;                    // 327680
    if (idx < NG) {
        int p = idx * 4;
        // ---- Acat ----
        {
            int e = p / (128 * Dsz);
            int r = p % (128 * Dsz);
            int n = r / Dsz, k = r % Dsz;                // k multiple of 4 (Dsz%4==0)
            const float* s = (n < Rsz)
                ? (A_exp + ((size_t)e * Rsz + n) * Dsz + k)
                : (A_gen + (size_t)(n - Rsz) * Dsz + k);
            float4 v = *(const float4*)s;
            uint2 o;
            o.x = h2u(__floats2half2_rn(v.x, v.y));
            o.y = h2u(__floats2half2_rn(v.z, v.w));
            *reinterpret_cast<uint2*>(&g_Acat[p]) = o;
        }
        // ---- Bcat (x2 folded) ----
        {
            int e2 = p / (Dsz * 128);
            int r2 = p % (Dsz * 128);
            int d = r2 / 128, k2 = r2 % 128;             // k2 multiple of 4
            const float* s = (k2 < Rsz)
                ? (B_exp + ((size_t)e2 * Dsz + d) * Rsz + k2)
                : (B_gen + (size_t)d * Rsz + (k2 - Rsz));
            float4 v = *(const float4*)s;
            uint2 o;
            o.x = h2u(__floats2half2_rn(2.0f * v.x, 2.0f * v.y));
            o.y = h2u(__floats2half2_rn(2.0f * v.z, 2.0f * v.w));
            *reinterpret_cast<uint2*>(&g_Bcat[p]) = o;
        }
    }
}

// ---------------------------------------------------------------------------
// GEMM1: H[b] (4096x128) = x[b] @ Acat[b]^T  (R13 mainloop — frozen).
// Epilogue: shfl_xor(1) pairs adjacent j half2 words -> STG.64 (half the
// store instructions and wavefronts).
// ---------------------------------------------------------------------------
__global__ __launch_bounds__(256, 2) void gemm1_fp16(
    const float* __restrict__ x,
    const int*   __restrict__ label)
{
    extern __shared__ char smem[];
    const int b   = blockIdx.y;
    const int m0  = blockIdx.x * 128;
    const int e   = __ldg(&label[b]);
    const int tid = threadIdx.x;
    const int warp = tid >> 5, lane = tid & 31;
    const int wm = warp & 3, wn = warp >> 2;
    const int lg = lane >> 2, lc = lane & 3;

    uint32_t sX = smem_u32(smem);
    uint32_t sA = sX + 2 * XSTG;

    const char* xb = (const char*)(x + ((size_t)b * Ssz + m0) * Dsz);
    const char* Ab = (const char*)g_Acat + (size_t)e * 128 * Dsz * 2;

    uint32_t xoff[2];
#pragma unroll
    for (int i = 0; i < 2; i++)
        xoff[i] = (uint32_t)((wm * 32 + i * 16 + lg) * 288 + lc * 8);

    uint32_t boff[4];
#pragma unroll
    for (int jp = 0; jp < 4; jp++)
        boff[jp] = (uint32_t)((wn * 64 + jp * 16 + (lane & 7) + ((lane >> 4) << 3)) * 144
                              + (((lane >> 3) & 1) << 4));

    auto stage = [&](int j) {
        uint32_t dX = sX + (j & 1) * XSTG;
        uint32_t dA = sA + (j & 1) * ASTG;
#pragma unroll
        for (int i = 0; i < 8; i++) {
            int cid = tid + i * 256;
            int row = cid >> 4, g = cid & 15;
            cp16(dX + row * 288 + g * 16, xb + (size_t)row * (Dsz * 4) + j * 256 + g * 16);
        }
#pragma unroll
        for (int i = 0; i < 4; i++) {
            int cid = tid + i * 256;
            int row = cid >> 3, g = cid & 7;
            cp16(dA + row * 144 + g * 16, Ab + (size_t)row * (Dsz * 2) + j * 128 + g * 16);
        }
        commit_group();
    };

    stage(0);
    stage(1);
    asm volatile("cp.async.wait_group 1;" ::: "memory");
    __syncthreads();

    float acc[2][8][4] = {};

    const int KT = Dsz / 64;    // 20
#pragma unroll 1
    for (int kt = 0; kt < KT; kt++) {
        uint32_t xS = sX + (kt & 1) * XSTG;
        uint32_t aS = sA + (kt & 1) * ASTG;

#pragma unroll
        for (int kk = 0; kk < 4; kk++) {
            unsigned af[2][4], bf[4][4];
#pragma unroll
            for (int i = 0; i < 2; i++) {
                uint32_t base = xS + xoff[i] + kk * 64;
                float2 p0 = lds64(base);
                float2 p1 = lds64(base + 8 * 288);
                float2 p2 = lds64(base + 32);
                float2 p3 = lds64(base + 8 * 288 + 32);
                af[i][0] = h2u(__floats2half2_rn(p0.x, p0.y));
                af[i][1] = h2u(__floats2half2_rn(p1.x, p1.y));
                af[i][2] = h2u(__floats2half2_rn(p2.x, p2.y));
                af[i][3] = h2u(__floats2half2_rn(p3.x, p3.y));
            }
#pragma unroll
            for (int jp = 0; jp < 4; jp++) ldsm_x4(bf[jp], aS + boff[jp] + kk * 32);
#pragma unroll
            for (int i = 0; i < 2; i++)
#pragma unroll
                for (int jp = 0; jp < 4; jp++) {
                    mma16816(acc[i][2*jp],   af[i], bf[jp][0], bf[jp][1]);
                    mma16816(acc[i][2*jp+1], af[i], bf[jp][2], bf[jp][3]);
                }
        }

        __syncthreads();
        if (kt + 2 < KT) stage(kt + 2);
        else             commit_group();
        asm volatile("cp.async.wait_group 1;" ::: "memory");
        __syncthreads();
    }

    // epilogue: H (fp16) -> global, shfl-merged to STG.64
    __half* Hb = g_H + ((size_t)b * Ssz + m0) * 128;
    const bool odd = (lc & 1);
#pragma unroll
    for (int i = 0; i < 2; i++) {
        int r = wm * 32 + i * 16 + lg;
#pragma unroll
        for (int jp2 = 0; jp2 < 4; jp2++) {
            int j0 = jp2 * 2, j1 = j0 + 1;
#pragma unroll
            for (int h = 0; h < 2; h++) {
                unsigned a0 = h2u(__floats2half2_rn(acc[i][j0][h*2], acc[i][j0][h*2+1]));
                unsigned a1 = h2u(__floats2half2_rn(acc[i][j1][h*2], acc[i][j1][h*2+1]));
                // even lanes keep j0 (need partner's j0); odd keep j1
                unsigned send = odd ? a0 : a1;
                unsigned recv = __shfl_xor_sync(0xffffffffu, send, 1);
                uint2 v;
                v.x = odd ? recv : a0;
                v.y = odd ? a1   : recv;
                int row = r + h * 8;
                int c2 = wn * 64 + (j0 + (lc & 1)) * 8 + (lc >> 1) * 4;   // halves
                *reinterpret_cast<uint2*>(Hb + (size_t)row * 128 + c2) = v;
            }
        }
    }
}

// ---------------------------------------------------------------------------
// GEMM2: out[b] (4096x1280) = H[b] @ Bcat[b]^T  (R14 — frozen).
// grid (32, 2, 32), 256 thr; each CTA does 5 of 10 n-tiles.
// ---------------------------------------------------------------------------
__global__ __launch_bounds__(256, 2) void gemm2_fp16(
    const int* __restrict__ label,
    float*     __restrict__ out)
{
    extern __shared__ char smem[];
    const int b   = blockIdx.z;
    const int ny  = blockIdx.y;
    const int m0  = blockIdx.x * 128;
    const int tid = threadIdx.x;
    const int nt0 = ny * 5;

    float* ob = out + ((size_t)b * Ssz + m0) * Dsz;

    if (b == Bsz - 1) {
        float4 z = make_float4(0.f, 0.f, 0.f, 0.f);
        float* obh = ob + ny * 640;
#pragma unroll 4
        for (int i = 0; i < 80; i++) {
            int v = tid + i * 256;
            int row = v / 160, c4 = v % 160;
            __stcs((float4*)(obh + (size_t)row * Dsz + c4 * 4), z);
        }
        return;
    }

    const int e = __ldg(&label[b]);
    const int warp = tid >> 5, lane = tid & 31;
    const int wm = warp & 3, wn = warp >> 2;
    const int lg = lane >> 2, lc = lane & 3;

    uint32_t sH = smem_u32(smem);
    uint32_t sB = sH + STGH;

    uint32_t aoff[2], boff[4];
#pragma unroll
    for (int i = 0; i < 2; i++)
        aoff[i] = (uint32_t)((wm * 32 + i * 16 + (lane & 15)) * 272 + ((lane >> 4) << 4));
#pragma unroll
    for (int jp = 0; jp < 4; jp++)
        boff[jp] = (uint32_t)((wn * 64 + jp * 16 + (lane & 7) + ((lane >> 4) << 3)) * 272
                              + (((lane >> 3) & 1) << 4));

    // H tile load (once)
    {
        const char* base = (const char*)g_H + ((size_t)b * Ssz + m0) * 256;
#pragma unroll
        for (int i = 0; i < 8; i++) {
            int cid = tid + i * 256;
            int row = cid >> 4, g = cid & 15;
            cp16(sH + row * 272 + g * 16, base + (size_t)row * 256 + g * 16);
        }
        commit_group();
    }

    auto cp_B = [&](int nt) {
        uint32_t dst = sB + (nt & 1) * STGH;
        const char* base = (const char*)g_Bcat + ((size_t)e * Dsz + nt * 128) * 256;
#pragma unroll
        for (int i = 0; i < 8; i++) {
            int cid = tid + i * 256;
            int row = cid >> 4, g = cid & 15;
            cp16(dst + row * 272 + g * 16, base + (size_t)row * 256 + g * 16);
        }
        commit_group();
    };

    cp_B(nt0);
    cp_B(nt0 + 1);
    asm volatile("cp.async.wait_group 1;" ::: "memory");   // H + B(nt0) ready
    __syncthreads();

#pragma unroll 1
    for (int t = 0; t < 5; t++) {
        const int nt = nt0 + t;
        float acc[2][8][4] = {};
        uint32_t bS = sB + (nt & 1) * STGH;

#pragma unroll
        for (int kk = 0; kk < 8; kk++) {
            unsigned af[2][4], bf[4][4];
            uint32_t kb = kk * 32;
#pragma unroll
            for (int i = 0; i < 2; i++) ldsm_x4(af[i], sH + aoff[i] + kb);
#pragma unroll
            for (int jp = 0; jp < 4; jp++) ldsm_x4(bf[jp], bS + boff[jp] + kb);
#pragma unroll
            for (int i = 0; i < 2; i++)
#pragma unroll
                for (int jp = 0; jp < 4; jp++) {
                    mma16816(acc[i][2*jp],   af[i], bf[jp][0], bf[jp][1]);
                    mma16816(acc[i][2*jp+1], af[i], bf[jp][2], bf[jp][3]);
                }
        }

        __syncthreads();
        if (t + 2 < 5) cp_B(nt + 2);
        else           commit_group();

        // epilogue: pair j-fragments via shfl, emit float4 (64B/row per instr)
        int n0 = nt * 128;
        const bool odd = (lc & 1);
#pragma unroll
        for (int i = 0; i < 2; i++) {
            int r = wm * 32 + i * 16 + lg;
#pragma unroll
            for (int jp2 = 0; jp2 < 4; jp2++) {
                int j0 = jp2 * 2, j1 = j0 + 1;
#pragma unroll
                for (int h = 0; h < 2; h++) {
                    float a0 = acc[i][j0][h*2], a1 = acc[i][j0][h*2+1];
                    float b0 = acc[i][j1][h*2], b1 = acc[i][j1][h*2+1];
                    float s0 = odd ? a0 : b0;
                    float s1 = odd ? a1 : b1;
                    float r0 = __shfl_xor_sync(0xffffffffu, s0, 1);
                    float r1 = __shfl_xor_sync(0xffffffffu, s1, 1);
                    float4 v = odd ? make_float4(r0, r1, b0, b1)
                                   : make_float4(a0, a1, r0, r1);
                    int row = r + h * 8;
                    int c = n0 + wn * 64 + (j0 + (lc & 1)) * 8 + (lc >> 1) * 4;
                    __stcs((float4*)&ob[(size_t)row * Dsz + c], v);
                }
            }
        }

        asm volatile("cp.async.wait_group 1;" ::: "memory");   // B(nt+1) complete
        __syncthreads();
    }
}

// ---------------------------------------------------------------------------
extern "C" void kernel_launch(void* const* d_in, const int* in_sizes, int n_in,
                              void* d_out, int out_size)
{
    const float* x     = (const float*)d_in[0];
    // d_in[1] = weight : unused by the reference
    const float* A_exp = (const float*)d_in[2];
    const float* B_exp = (const float*)d_in[3];
    const float* A_gen = (const float*)d_in[4];
    const float* B_gen = (const float*)d_in[5];
    const int*   label = (const int*)d_in[6];
    float* out = (float*)d_out;

    cudaFuncSetAttribute(gemm1_fp16, cudaFuncAttributeMaxDynamicSharedMemorySize, SMEM1);
    cudaFuncSetAttribute(gemm2_fp16, cudaFuncAttributeMaxDynamicSharedMemorySize, SMEM2);

    preconv_kernel<<<(8 * 128 * Dsz / 4 + 255) / 256, 256>>>(A_exp, B_exp, A_gen, B_gen);
    gemm1_fp16<<<dim3(Ssz / 128, Bsz - 1), 256, SMEM1>>>(x, label);
    gemm2_fp16<<<dim3(Ssz / 128, 2, Bsz), 256, SMEM2>>>(label, out);
}